// round 14
// baseline (speedup 1.0000x reference)
#include <cuda_runtime.h>
#include <cuda_fp16.h>
#include <math.h>
#include <stdint.h>

// VanillaLSTM persistent kernel (sm_103 HMMA fp16), split-K x4 warps.
// 96 CTAs x 1024 threads (32 warps, 8/SMSP). h fp16, W fp16.
// Warp (rw, kq): rows [16rw,16rw+16), K-chunks [3kq, 3kq+3). Partials reduced
// 4-way via SMEM + one 128-thread named barrier per row-warp; warp keeps
// n-tile kq for the epilogue. Depth-2 cp.async A pipeline per warp.
// Dataflow sync: 12 per-CTA-group counters, 1 release/CTA/step (R13 scheme).

#define ROWS 128
#define HDIM 768
#define SEQ  256
#define NCTA 96
#define NCHUNK 12

// smem layout (bytes)
#define WS_BASE 0                 // 12 chunks * 32 rows * 128B = 48KB
#define A_BASE 49152              // 32 warps * 2 bufs * 2048 = 128KB
#define FLAG_OFF (A_BASE + 32 * 2 * 2048)     // 180224
#define SMEM_TOTAL (FLAG_OFF + 128)           // 180352

__device__ __align__(16) __half        g_h[2][ROWS * HDIM];
__device__ __align__(16) float         g_c[ROWS * HDIM];
__device__ __align__(16) __half        g_W[NCTA * NCHUNK * 2048];   // pre-swizzled
__device__ __align__(16) float2        g_wxb[NCTA * 32];
__device__ __align__(128) unsigned     g_ctr[NCHUNK][32];   // one per CTA group

// ---------------------------------------------------------------------------
__device__ __forceinline__ uint32_t smem_u32(const void* p) {
    uint32_t a;
    asm("{ .reg .u64 t; cvta.to.shared.u64 t, %1; cvt.u32.u64 %0, t; }" : "=r"(a) : "l"(p));
    return a;
}
__device__ __forceinline__ void cpa16(uint32_t dst, const void* src) {
    asm volatile("cp.async.cg.shared.global [%0], [%1], 16;" :: "r"(dst), "l"(src) : "memory");
}
__device__ __forceinline__ void cp_commit() {
    asm volatile("cp.async.commit_group;" ::: "memory");
}
__device__ __forceinline__ void cp_wait1() {
    asm volatile("cp.async.wait_group 1;" ::: "memory");
}
__device__ __forceinline__ void cp_wait0() {
    asm volatile("cp.async.wait_group 0;" ::: "memory");
}
__device__ __forceinline__ void ldsm4(uint32_t* r, uint32_t addr) {
    asm volatile("ldmatrix.sync.aligned.m8n8.x4.shared.b16 {%0,%1,%2,%3}, [%4];"
                 : "=r"(r[0]), "=r"(r[1]), "=r"(r[2]), "=r"(r[3]) : "r"(addr));
}
__device__ __forceinline__ void mma_f16(float* d, const uint32_t* a, uint32_t b0, uint32_t b1) {
    asm volatile(
        "mma.sync.aligned.m16n8k16.row.col.f32.f16.f16.f32 "
        "{%0,%1,%2,%3}, {%4,%5,%6,%7}, {%8,%9}, {%0,%1,%2,%3};"
        : "+f"(d[0]), "+f"(d[1]), "+f"(d[2]), "+f"(d[3])
        : "r"(a[0]), "r"(a[1]), "r"(a[2]), "r"(a[3]), "r"(b0), "r"(b1));
}

// ---------------------------------------------------------------------------
__global__ void init_state(const float* __restrict__ h0, const float* __restrict__ c0) {
    int i = blockIdx.x * 256 + threadIdx.x;
    if (i < NCHUNK) g_ctr[i][0] = 0u;
    if (i < ROWS * HDIM) {
        g_h[0][i] = __float2half(h0[i]);
        g_c[i] = c0[i];
    }
}

// ---------------------------------------------------------------------------
// Repack weights pre-swizzled fp16: elem (blk, n, kl) ->
//   blk*2048 + n*64 + ((kl>>3) ^ (n&7))*8 + (kl&7)
__global__ void repack(const float* __restrict__ Wi, const float* __restrict__ Wf,
                       const float* __restrict__ Wc, const float* __restrict__ Wo,
                       const float* __restrict__ bi, const float* __restrict__ bf,
                       const float* __restrict__ bc, const float* __restrict__ bo) {
    int idx = blockIdx.x * 256 + threadIdx.x;
    const int TOT = NCTA * NCHUNK * 2048;
    if (idx < TOT) {
        int kl  = idx & 63;
        int n   = (idx >> 6) & 31;
        int blk = idx >> 11;
        int kc  = blk % NCHUNK;
        int nb  = blk / NCHUNK;
        int gate = n & 3;
        int j = nb * 8 + (n >> 2);
        const float* W = (gate == 0) ? Wi : (gate == 1) ? Wf : (gate == 2) ? Wc : Wo;
        float v = W[(1 + kc * 64 + kl) * HDIM + j];
        int dst = blk * 2048 + n * 64 + (((kl >> 3) ^ (n & 7)) << 3) + (kl & 7);
        g_W[dst] = __float2half(v);
    }
    if (idx < NCTA * 32) {
        int n = idx & 31;
        int nb = idx >> 5;
        int gate = n & 3;
        int j = nb * 8 + (n >> 2);
        const float* W = (gate == 0) ? Wi : (gate == 1) ? Wf : (gate == 2) ? Wc : Wo;
        const float* B = (gate == 0) ? bi : (gate == 1) ? bf : (gate == 2) ? bc : bo;
        g_wxb[idx] = make_float2(W[j], B[j]);
    }
}

// ---------------------------------------------------------------------------
__global__ void __launch_bounds__(1024, 1) lstm_persistent(const float* __restrict__ x) {
    extern __shared__ char smem[];
    const uint32_t sb = smem_u32(smem);
    const int tid = threadIdx.x;
    const int lane = tid & 31, wid = tid >> 5;
    const int rw = wid & 7;          // row-warp: rows [16rw, 16rw+16)
    const int kq = wid >> 3;         // K-quarter: chunks [3kq, 3kq+3)
    const int nb = blockIdx.x;
    const uint32_t flag_addr = sb + FLAG_OFF;

    // ---------------- prologue: stage W into smem (contiguous, pre-swizzled) --
    {
        const uint4* __restrict__ sw = ((const uint4*)g_W) + nb * 3072;
        uint4* dw = (uint4*)(smem + WS_BASE);
        for (int i = tid; i < 3072; i += 1024) dw[i] = sw[i];
        if (tid == 0) *(volatile unsigned*)(smem + FLAG_OFF) = 0u;
    }
    __syncthreads();

    const uint32_t abase = sb + A_BASE + (uint32_t)wid * 4096;  // 2 bufs x 2048

    // ldsm lane constants (XOR swizzle, pitch 128)
    const int sel = lane >> 3, li = lane & 7;
    const int hsA = sel >> 1, hsB = sel & 1;
    const uint32_t aoffrow = (uint32_t)((li + (sel & 1) * 8) * 128);
    const uint32_t boffrow = (uint32_t)((li + (sel >> 1) * 8) * 128);

    // epilogue constants (this warp epilogues n-tile kq only)
    const int my_row = rw * 16 + (lane >> 2) + (lane & 1) * 8;
    const float* __restrict__ xrow = x + (my_row >> 1) * 512 + (my_row & 1);
    const int jl = kq * 2 + ((lane & 3) >> 1);

    float2 wxi, wxf, wxc, wxo;
    float  creg;
    {
        const float2* __restrict__ wxbp = g_wxb + nb * 32;
        wxi = wxbp[4 * jl + 0];
        wxf = wxbp[4 * jl + 1];
        wxc = wxbp[4 * jl + 2];
        wxo = wxbp[4 * jl + 3];
        creg = g_c[my_row * HDIM + nb * 8 + jl];
    }

    // sync: ONE counter per CTA group (12). Warp 0 lanes 0-11 poll, lane 0
    // publishes flag; workers spin on SMEM flag. One release per CTA per step.
    unsigned* __restrict__ relp = &g_ctr[nb >> 3][0];
    const unsigned* __restrict__ pollp =
        (lane < NCHUNK) ? &g_ctr[lane][0] : &g_ctr[0][0];

    for (int t = 0; t < SEQ; ++t) {
        const int par = t & 1;
        const __half* __restrict__ hin = g_h[par];
        __half* __restrict__ hout = g_h[par ^ 1];

        // ---- dataflow wait ----
        if (t > 0) {
            const unsigned tgt = 8u * (unsigned)t;
            if (wid == 0) {
                for (;;) {
                    unsigned v = tgt;
                    if (lane < NCHUNK) {
                        asm volatile("ld.acquire.gpu.global.u32 %0, [%1];"
                                     : "=r"(v) : "l"(pollp) : "memory");
                    }
                    if (__all_sync(0xffffffffu, v >= tgt)) break;
                }
                if (lane == 0) {
                    asm volatile("st.release.cta.shared.u32 [%0], %1;"
                                 :: "r"(flag_addr), "r"((unsigned)t) : "memory");
                }
                __syncwarp();
            } else {
                unsigned v;
                do {
                    asm volatile("ld.acquire.cta.shared.u32 %0, [%1];"
                                 : "=r"(v) : "r"(flag_addr) : "memory");
                } while (v < (unsigned)t);
            }
        }
        __syncwarp();

        float d[4][4];
#pragma unroll
        for (int i = 0; i < 4; i++)
#pragma unroll
            for (int k = 0; k < 4; k++) d[i][k] = 0.f;

        // per-warp A staging: 16 rows x 64 k fp16, XOR swizzle, buffer l&1
        auto issue = [&](int l) {
            const int g = kq * 3 + l;
            const uint32_t bufs = abase + (uint32_t)(l & 1) * 2048;
#pragma unroll
            for (int i = 0; i < 4; ++i) {
                int o = lane * 4 + i;            // 0..127
                int row = o >> 3, seg = o & 7;
                uint32_t dst = bufs + (uint32_t)(row * 128 + ((seg ^ (row & 7)) << 4));
                cpa16(dst, hin + (rw * 16 + row) * HDIM + g * 64 + seg * 8);
            }
            cp_commit();
        };

        issue(0); issue(1);

#pragma unroll
        for (int l = 0; l < 3; ++l) {
            if (l < 2) cp_wait1(); else cp_wait0();
            __syncwarp();
            const int g = kq * 3 + l;
            const uint32_t abuf = abase + (uint32_t)(l & 1) * 2048;
            const uint32_t wch = sb + WS_BASE + (uint32_t)g * 4096;
#pragma unroll
            for (int ks = 0; ks < 4; ++ks) {
                const uint32_t asw = (uint32_t)((((ks << 1) | hsA) ^ li) << 4);
                const uint32_t bsw = (uint32_t)((((ks << 1) | hsB) ^ li) << 4);
                uint32_t a[4];
                ldsm4(a, abuf + aoffrow + asw);
#pragma unroll
                for (int p = 0; p < 2; ++p) {
                    uint32_t b[4];
                    ldsm4(b, wch + boffrow + (uint32_t)(p * 2048) + bsw);
                    mma_f16(d[2 * p],     a, b[0], b[1]);
                    mma_f16(d[2 * p + 1], a, b[2], b[3]);
                }
            }
            __syncwarp();
            if (l + 2 < 3) issue(l + 2);
        }

        // ---------------- split-K 4-way partial reduce --------------------
        // Store all 16 partials in [col][lane] layout (conflict-free); the 4
        // warps sharing rw meet at named barrier 1+rw (128 threads); each warp
        // keeps n-tile kq = own partial + 3 partners' kq-slices.
        {
            float* ex = (float*)(smem + A_BASE + (uint32_t)wid * 4096);
#pragma unroll
            for (int nt = 0; nt < 4; ++nt)
#pragma unroll
                for (int k = 0; k < 4; ++k) ex[(nt * 4 + k) * 32 + lane] = d[nt][k];
            asm volatile("bar.sync %0, 128;" :: "r"(1 + rw) : "memory");
#pragma unroll
            for (int j = 0; j < 4; ++j) {
                if (j == kq) continue;
                const float* px = (const float*)(smem + A_BASE + (uint32_t)(rw + 8 * j) * 4096);
#pragma unroll
                for (int k = 0; k < 4; ++k) d[kq][k] += px[(kq * 4 + k) * 32 + lane];
            }
        }

        // ---------------- fused LSTM epilogue (n-tile kq) ------------------
        {
            const float xv = xrow[2 * t];
            float p0 = __shfl_xor_sync(0xffffffffu, d[kq][0], 1);
            float p1 = __shfl_xor_sync(0xffffffffu, d[kq][1], 1);
            float p2 = __shfl_xor_sync(0xffffffffu, d[kq][2], 1);
            float p3 = __shfl_xor_sync(0xffffffffu, d[kq][3], 1);
            float gi, gf, gc, go;
            if (!(lane & 1)) { gi = d[kq][0]; gf = d[kq][1]; gc = p0; go = p1; }
            else             { gi = p2;       gf = p3;       gc = d[kq][2]; go = d[kq][3]; }
            float pi = gi + xv * wxi.x + wxi.y;
            float pf = gf + xv * wxf.x + wxf.y;
            float pc = gc + xv * wxc.x + wxc.y;
            float po = go + xv * wxo.x + wxo.y;
            float ig = __fdividef(1.f, 1.f + __expf(-pi));
            float fg = __fdividef(1.f, 1.f + __expf(-pf));
            float thc = 1.f - __fdividef(2.f, 1.f + __expf(2.f * pc));
            float cn = fg * creg + ig * thc;
            float thn = 1.f - __fdividef(2.f, 1.f + __expf(2.f * cn));
            float hn = po * thn;            // no sigmoid on output gate
            creg = cn;
            hout[my_row * HDIM + nb * 8 + jl] = __float2half(hn);
        }

        // publish: CTA-wide sync orders all warps' h stores (and exchange
        // reads, protecting ex-buffer reuse as A buffer 0 next step) before
        // the single release-add by thread 0.
        if (t + 1 < SEQ) {
            __syncthreads();
            if (tid == 0) {
                asm volatile("red.release.gpu.global.add.u32 [%0], %1;"
                             :: "l"(relp), "r"(1u) : "memory");
            }
        }
    }
}

// ---------------------------------------------------------------------------
__global__ void out_final(const float* __restrict__ Wout,
                          const float* __restrict__ bout,
                          float* __restrict__ out) {
    int gtid = blockIdx.x * 128 + threadIdx.x;
    int r = gtid >> 5, lane = gtid & 31;
    float s = 0.f;
    for (int k = lane; k < HDIM; k += 32)
        s += __half2float(g_h[0][r * HDIM + k]) * Wout[k];
#pragma unroll
    for (int o = 16; o; o >>= 1) s += __shfl_xor_sync(0xffffffffu, s, o);
    if (lane == 0) out[r] = s + bout[0];
}

// ---------------------------------------------------------------------------
extern "C" void kernel_launch(void* const* d_in, const int* in_sizes, int n_in,
                              void* d_out, int out_size) {
    (void)in_sizes; (void)n_in; (void)out_size;
    const float* x    = (const float*)d_in[0];
    const float* h0   = (const float*)d_in[1];
    const float* c0   = (const float*)d_in[2];
    const float* Wi   = (const float*)d_in[3];
    const float* bi   = (const float*)d_in[4];
    const float* Wf   = (const float*)d_in[5];
    const float* bf   = (const float*)d_in[6];
    const float* Wc   = (const float*)d_in[7];
    const float* bc   = (const float*)d_in[8];
    const float* Wo   = (const float*)d_in[9];
    const float* bo   = (const float*)d_in[10];
    const float* Wout = (const float*)d_in[11];
    const float* bout = (const float*)d_in[12];
    float* out = (float*)d_out;

    static int configured = 0;
    if (!configured) {
        cudaFuncSetAttribute(lstm_persistent,
                             cudaFuncAttributeMaxDynamicSharedMemorySize, SMEM_TOTAL);
        configured = 1;
    }

    init_state<<<(ROWS * HDIM + 255) / 256, 256>>>(h0, c0);
    repack<<<(NCTA * NCHUNK * 2048 + 255) / 256, 256>>>(Wi, Wf, Wc, Wo, bi, bf, bc, bo);
    lstm_persistent<<<NCTA, 1024, SMEM_TOTAL>>>(x);
    out_final<<<32, 128>>>(Wout, bout, out);
}

// round 15
// speedup vs baseline: 1.1186x; 1.1186x over previous
#include <cuda_runtime.h>
#include <cuda_fp16.h>
#include <math.h>
#include <stdint.h>

// VanillaLSTM persistent kernel (sm_103 HMMA fp16 single-W), split-K warps.
// 96 CTAs x 512 threads (R13 structure). h fp16, W fp16. Warps rw / rw+8 split
// K (chunks 0-5 / 6-11), partials merged via SMEM + 64-thread named barrier.
// R15: depth-4 cp.async A pipeline with next-chunk issue hoisted BEFORE the
// MMA block (loads ride in the MMA shadow). Coarse dataflow sync (R13): 12
// per-CTA-group counters, one release per CTA per step, warp-0 poll + flag.

#define ROWS 128
#define HDIM 768
#define SEQ  256
#define NCTA 96
#define NCHUNK 12

// smem layout (bytes)
#define WS_BASE 0                // 12 chunks * 32 rows * 128B (fp16) = 48KB
#define A_BASE 49152             // 16 warps * 4 bufs * 2048 = 128KB
#define FLAG_OFF (A_BASE + 16 * 4 * 2048)     // 180224
#define SMEM_TOTAL (FLAG_OFF + 128)           // 180352

__device__ __align__(16) __half        g_h[2][ROWS * HDIM];
__device__ __align__(16) float         g_c[ROWS * HDIM];
__device__ __align__(16) __half        g_W[NCTA * NCHUNK * 2048];   // pre-swizzled
__device__ __align__(16) float2        g_wxb[NCTA * 32];
__device__ __align__(128) unsigned     g_ctr[NCHUNK][32];   // one per CTA group

// ---------------------------------------------------------------------------
__device__ __forceinline__ uint32_t smem_u32(const void* p) {
    uint32_t a;
    asm("{ .reg .u64 t; cvta.to.shared.u64 t, %1; cvt.u32.u64 %0, t; }" : "=r"(a) : "l"(p));
    return a;
}
__device__ __forceinline__ void cpa16(uint32_t dst, const void* src) {
    asm volatile("cp.async.cg.shared.global [%0], [%1], 16;" :: "r"(dst), "l"(src) : "memory");
}
__device__ __forceinline__ void cp_commit() {
    asm volatile("cp.async.commit_group;" ::: "memory");
}
__device__ __forceinline__ void cp_wait2() {
    asm volatile("cp.async.wait_group 2;" ::: "memory");
}
__device__ __forceinline__ void cp_wait1() {
    asm volatile("cp.async.wait_group 1;" ::: "memory");
}
__device__ __forceinline__ void cp_wait0() {
    asm volatile("cp.async.wait_group 0;" ::: "memory");
}
__device__ __forceinline__ void ldsm4(uint32_t* r, uint32_t addr) {
    asm volatile("ldmatrix.sync.aligned.m8n8.x4.shared.b16 {%0,%1,%2,%3}, [%4];"
                 : "=r"(r[0]), "=r"(r[1]), "=r"(r[2]), "=r"(r[3]) : "r"(addr));
}
__device__ __forceinline__ void mma_f16(float* d, const uint32_t* a, uint32_t b0, uint32_t b1) {
    asm volatile(
        "mma.sync.aligned.m16n8k16.row.col.f32.f16.f16.f32 "
        "{%0,%1,%2,%3}, {%4,%5,%6,%7}, {%8,%9}, {%0,%1,%2,%3};"
        : "+f"(d[0]), "+f"(d[1]), "+f"(d[2]), "+f"(d[3])
        : "r"(a[0]), "r"(a[1]), "r"(a[2]), "r"(a[3]), "r"(b0), "r"(b1));
}

// ---------------------------------------------------------------------------
__global__ void init_state(const float* __restrict__ h0, const float* __restrict__ c0) {
    int i = blockIdx.x * 256 + threadIdx.x;
    if (i < NCHUNK) g_ctr[i][0] = 0u;
    if (i < ROWS * HDIM) {
        g_h[0][i] = __float2half(h0[i]);
        g_c[i] = c0[i];
    }
}

// ---------------------------------------------------------------------------
// Repack weights pre-swizzled fp16: elem (blk, n, kl) ->
//   blk*2048 + n*64 + ((kl>>3) ^ (n&7))*8 + (kl&7)
__global__ void repack(const float* __restrict__ Wi, const float* __restrict__ Wf,
                       const float* __restrict__ Wc, const float* __restrict__ Wo,
                       const float* __restrict__ bi, const float* __restrict__ bf,
                       const float* __restrict__ bc, const float* __restrict__ bo) {
    int idx = blockIdx.x * 256 + threadIdx.x;
    const int TOT = NCTA * NCHUNK * 2048;
    if (idx < TOT) {
        int kl  = idx & 63;
        int n   = (idx >> 6) & 31;
        int blk = idx >> 11;
        int kc  = blk % NCHUNK;
        int nb  = blk / NCHUNK;
        int gate = n & 3;
        int j = nb * 8 + (n >> 2);
        const float* W = (gate == 0) ? Wi : (gate == 1) ? Wf : (gate == 2) ? Wc : Wo;
        float v = W[(1 + kc * 64 + kl) * HDIM + j];
        int dst = blk * 2048 + n * 64 + (((kl >> 3) ^ (n & 7)) << 3) + (kl & 7);
        g_W[dst] = __float2half(v);
    }
    if (idx < NCTA * 32) {
        int n = idx & 31;
        int nb = idx >> 5;
        int gate = n & 3;
        int j = nb * 8 + (n >> 2);
        const float* W = (gate == 0) ? Wi : (gate == 1) ? Wf : (gate == 2) ? Wc : Wo;
        const float* B = (gate == 0) ? bi : (gate == 1) ? bf : (gate == 2) ? bc : bo;
        g_wxb[idx] = make_float2(W[j], B[j]);
    }
}

// ---------------------------------------------------------------------------
__global__ void __launch_bounds__(512, 1) lstm_persistent(const float* __restrict__ x) {
    extern __shared__ char smem[];
    const uint32_t sb = smem_u32(smem);
    const int tid = threadIdx.x;
    const int lane = tid & 31, wid = tid >> 5;
    const int rw = wid & 7;          // row-warp: rows [16rw, 16rw+16)
    const int hf = wid >> 3;         // K-half: chunks [6hf, 6hf+6)
    const int nb = blockIdx.x;
    const uint32_t flag_addr = sb + FLAG_OFF;

    // ---------------- prologue: stage W into smem (contiguous, pre-swizzled) --
    {
        const uint4* __restrict__ sw = ((const uint4*)g_W) + nb * 3072;
        uint4* dw = (uint4*)(smem + WS_BASE);
        for (int i = tid; i < 3072; i += 512) dw[i] = sw[i];
        if (tid == 0) *(volatile unsigned*)(smem + FLAG_OFF) = 0u;
    }
    __syncthreads();

    const uint32_t abase = sb + A_BASE + (uint32_t)wid * 8192;  // 4 bufs x 2048

    // ldsm lane constants (XOR swizzle, pitch 128)
    const int sel = lane >> 3, li = lane & 7;
    const int hsA = sel >> 1, hsB = sel & 1;
    const uint32_t aoffrow = (uint32_t)((li + (sel & 1) * 8) * 128);
    const uint32_t boffrow = (uint32_t)((li + (sel >> 1) * 8) * 128);

    // epilogue constants
    const int my_row = rw * 16 + (lane >> 2) + (lane & 1) * 8;
    const float* __restrict__ xrow = x + (my_row >> 1) * 512 + (my_row & 1);
    const int ntK = (hf == 0) ? 0 : 2;    // kept n-tiles
    const int ntS = 2 - ntK;              // sent n-tiles

    // registers: wxb + cell state for kept n-tiles
    float2 wxi[2], wxf[2], wxc[2], wxo[2];
    float  creg[2];
    {
        const float2* __restrict__ wxbp = g_wxb + nb * 32;
#pragma unroll
        for (int q = 0; q < 2; ++q) {
            int jl = (ntK + q) * 2 + ((lane & 3) >> 1);
            wxi[q] = wxbp[4 * jl + 0];
            wxf[q] = wxbp[4 * jl + 1];
            wxc[q] = wxbp[4 * jl + 2];
            wxo[q] = wxbp[4 * jl + 3];
            creg[q] = g_c[my_row * HDIM + nb * 8 + jl];
        }
    }

    // sync: ONE counter per CTA group (12). Warp 0 lanes 0-11 poll, lane 0
    // publishes flag; workers spin on SMEM flag. One release per CTA per step.
    unsigned* __restrict__ relp = &g_ctr[nb >> 3][0];
    const unsigned* __restrict__ pollp =
        (lane < NCHUNK) ? &g_ctr[lane][0] : &g_ctr[0][0];

    for (int t = 0; t < SEQ; ++t) {
        const int par = t & 1;
        const __half* __restrict__ hin = g_h[par];
        __half* __restrict__ hout = g_h[par ^ 1];

        // ---- dataflow wait ----
        if (t > 0) {
            const unsigned tgt = 8u * (unsigned)t;
            if (wid == 0) {
                for (;;) {
                    unsigned v = tgt;
                    if (lane < NCHUNK) {
                        asm volatile("ld.acquire.gpu.global.u32 %0, [%1];"
                                     : "=r"(v) : "l"(pollp) : "memory");
                    }
                    if (__all_sync(0xffffffffu, v >= tgt)) break;
                }
                if (lane == 0) {
                    asm volatile("st.release.cta.shared.u32 [%0], %1;"
                                 :: "r"(flag_addr), "r"((unsigned)t) : "memory");
                }
                __syncwarp();
            } else {
                unsigned v;
                do {
                    asm volatile("ld.acquire.cta.shared.u32 %0, [%1];"
                                 : "=r"(v) : "r"(flag_addr) : "memory");
                } while (v < (unsigned)t);
            }
        }
        __syncwarp();

        float d[4][4];
#pragma unroll
        for (int i = 0; i < 4; i++)
#pragma unroll
            for (int k = 0; k < 4; k++) d[i][k] = 0.f;

        // per-warp A staging: 16 rows x 64 k fp16, XOR swizzle, buffer l%4
        auto issue = [&](int l) {
            const int g = hf * 6 + l;
            const uint32_t bufs = abase + (uint32_t)(l & 3) * 2048;
#pragma unroll
            for (int i = 0; i < 4; ++i) {
                int o = lane * 4 + i;            // 0..127
                int row = o >> 3, seg = o & 7;
                uint32_t dst = bufs + (uint32_t)(row * 128 + ((seg ^ (row & 7)) << 4));
                cpa16(dst, hin + (rw * 16 + row) * HDIM + g * 64 + seg * 8);
            }
            cp_commit();
        };

        issue(0); issue(1); issue(2);

#pragma unroll
        for (int l = 0; l < 6; ++l) {
            // wait for buffer l, keeping up to 2 younger groups in flight
            if (l < 4)       cp_wait2();
            else if (l == 4) cp_wait1();
            else             cp_wait0();
            __syncwarp();
            // hoist next-chunk loads BEFORE the MMA block (depth-4: no buffer
            // conflict — issue(l+3) writes buf (l+3)&3 != l&3)
            if (l + 3 < 6) issue(l + 3);
            const int g = hf * 6 + l;
            const uint32_t abuf = abase + (uint32_t)(l & 3) * 2048;
            const uint32_t wch = sb + WS_BASE + (uint32_t)g * 4096;
#pragma unroll
            for (int ks = 0; ks < 4; ++ks) {
                const uint32_t asw = (uint32_t)((((ks << 1) | hsA) ^ li) << 4);
                const uint32_t bsw = (uint32_t)((((ks << 1) | hsB) ^ li) << 4);
                uint32_t a[4];
                ldsm4(a, abuf + aoffrow + asw);
#pragma unroll
                for (int p = 0; p < 2; ++p) {
                    uint32_t b[4];
                    ldsm4(b, wch + boffrow + (uint32_t)(p * 2048) + bsw);
                    mma_f16(d[2 * p],     a, b[0], b[1]);
                    mma_f16(d[2 * p + 1], a, b[2], b[3]);
                }
            }
            __syncwarp();
        }

        // ---------------- split-K partial exchange (warp pair rw, rw+8) -------
        // exchange buffer = own A buf0 region (all chunks consumed). Partner's
        // read is ordered before next-step overwrite by the publish
        // __syncthreads below (single bar here suffices).
        {
            float* ex = (float*)(smem + A_BASE + (uint32_t)wid * 8192 + lane * 32);
#pragma unroll
            for (int k = 0; k < 4; ++k) { ex[k] = d[ntS][k]; ex[4 + k] = d[ntS + 1][k]; }
            asm volatile("bar.sync %0, 64;" :: "r"(1 + rw) : "memory");
            const float* px = (const float*)(smem + A_BASE + (uint32_t)(wid ^ 8) * 8192 + lane * 32);
#pragma unroll
            for (int k = 0; k < 4; ++k) { d[ntK][k] += px[k]; d[ntK + 1][k] += px[4 + k]; }
        }

        // ---------------- fused LSTM epilogue (kept n-tiles) ------------------
        const float xv = xrow[2 * t];
#pragma unroll
        for (int q = 0; q < 2; ++q) {
            const int nt = ntK + q;
            const int jl = nt * 2 + ((lane & 3) >> 1);
            float p0 = __shfl_xor_sync(0xffffffffu, d[nt][0], 1);
            float p1 = __shfl_xor_sync(0xffffffffu, d[nt][1], 1);
            float p2 = __shfl_xor_sync(0xffffffffu, d[nt][2], 1);
            float p3 = __shfl_xor_sync(0xffffffffu, d[nt][3], 1);
            float gi, gf, gc, go;
            if (!(lane & 1)) { gi = d[nt][0]; gf = d[nt][1]; gc = p0; go = p1; }
            else             { gi = p2;       gf = p3;       gc = d[nt][2]; go = d[nt][3]; }
            float pi = gi + xv * wxi[q].x + wxi[q].y;
            float pf = gf + xv * wxf[q].x + wxf[q].y;
            float pc = gc + xv * wxc[q].x + wxc[q].y;
            float po = go + xv * wxo[q].x + wxo[q].y;
            float ig = __fdividef(1.f, 1.f + __expf(-pi));
            float fg = __fdividef(1.f, 1.f + __expf(-pf));
            float thc = 1.f - __fdividef(2.f, 1.f + __expf(2.f * pc));
            float cn = fg * creg[q] + ig * thc;
            float thn = 1.f - __fdividef(2.f, 1.f + __expf(2.f * cn));
            float hn = po * thn;            // no sigmoid on output gate
            creg[q] = cn;
            hout[my_row * HDIM + nb * 8 + jl] = __float2half(hn);
        }

        // publish: CTA-wide sync orders all warps' h stores (and exchange
        // reads) before the single release-add by thread 0.
        if (t + 1 < SEQ) {
            __syncthreads();
            if (tid == 0) {
                asm volatile("red.release.gpu.global.add.u32 [%0], %1;"
                             :: "l"(relp), "r"(1u) : "memory");
            }
        }
    }
}

// ---------------------------------------------------------------------------
__global__ void out_final(const float* __restrict__ Wout,
                          const float* __restrict__ bout,
                          float* __restrict__ out) {
    int gtid = blockIdx.x * 128 + threadIdx.x;
    int r = gtid >> 5, lane = gtid & 31;
    float s = 0.f;
    for (int k = lane; k < HDIM; k += 32)
        s += __half2float(g_h[0][r * HDIM + k]) * Wout[k];
#pragma unroll
    for (int o = 16; o; o >>= 1) s += __shfl_xor_sync(0xffffffffu, s, o);
    if (lane == 0) out[r] = s + bout[0];
}

// ---------------------------------------------------------------------------
extern "C" void kernel_launch(void* const* d_in, const int* in_sizes, int n_in,
                              void* d_out, int out_size) {
    (void)in_sizes; (void)n_in; (void)out_size;
    const float* x    = (const float*)d_in[0];
    const float* h0   = (const float*)d_in[1];
    const float* c0   = (const float*)d_in[2];
    const float* Wi   = (const float*)d_in[3];
    const float* bi   = (const float*)d_in[4];
    const float* Wf   = (const float*)d_in[5];
    const float* bf   = (const float*)d_in[6];
    const float* Wc   = (const float*)d_in[7];
    const float* bc   = (const float*)d_in[8];
    const float* Wo   = (const float*)d_in[9];
    const float* bo   = (const float*)d_in[10];
    const float* Wout = (const float*)d_in[11];
    const float* bout = (const float*)d_in[12];
    float* out = (float*)d_out;

    static int configured = 0;
    if (!configured) {
        cudaFuncSetAttribute(lstm_persistent,
                             cudaFuncAttributeMaxDynamicSharedMemorySize, SMEM_TOTAL);
        configured = 1;
    }

    init_state<<<(ROWS * HDIM + 255) / 256, 256>>>(h0, c0);
    repack<<<(NCTA * NCHUNK * 2048 + 255) / 256, 256>>>(Wi, Wf, Wc, Wo, bi, bf, bc, bo);
    lstm_persistent<<<NCTA, 512, SMEM_TOTAL>>>(x);
    out_final<<<32, 128>>>(Wout, bout, out);
}

// round 16
// speedup vs baseline: 1.4267x; 1.2754x over previous
#include <cuda_runtime.h>
#include <cuda_fp16.h>
#include <math.h>
#include <stdint.h>

// VanillaLSTM persistent kernel (sm_103 HMMA fp16), 2D row x unit partition.
// 96 CTAs = 4 row-groups (32 rows) x 24 unit-blocks (32 hidden units, N=128
// gate cols). Full K=768 per CTA; W slice (192KB fp16) SMEM-resident.
// The LSTM recurrence is row-independent -> the 4 row-groups are fully
// independent recurrences; sync = 1 counter per group, 24 CTAs each.
// A (32 rows x 768) staged CTA-wide in 6 chunks of 128k (8KB), depth-3
// cp.async, one __syncthreads per chunk. 512 threads: warp (mw,nw) = rows
// [16mw,16mw+16) x gate cols [16nw,16nw+16), 96 HMMA/warp/step.

#define ROWS 128
#define HDIM 768
#define SEQ  256
#define NCTA 96
#define NJ   24      // unit blocks
#define NG   4       // row groups

// smem layout (bytes)
#define WS_BASE 0                 // 12 blocks x 16KB = 196608
#define A_BASE 196608             // 3 bufs x 8192 = 24576
#define FLAG_OFF 221184
#define SMEM_TOTAL 221312

__device__ __align__(16) __half        g_h[2][ROWS * HDIM];
__device__ __align__(16) float         g_c[ROWS * HDIM];
__device__ __align__(16) __half        g_W[NJ * 98304];     // [j][g(12)][n(128)][kl(64) swizzled]
__device__ __align__(16) float2        g_wxb[NJ * 128];     // [j][n]: (W_row0, bias)
__device__ __align__(128) unsigned     g_ctr[NG][32];       // one per row-group

// ---------------------------------------------------------------------------
__device__ __forceinline__ uint32_t smem_u32(const void* p) {
    uint32_t a;
    asm("{ .reg .u64 t; cvta.to.shared.u64 t, %1; cvt.u32.u64 %0, t; }" : "=r"(a) : "l"(p));
    return a;
}
__device__ __forceinline__ void cpa16(uint32_t dst, const void* src) {
    asm volatile("cp.async.cg.shared.global [%0], [%1], 16;" :: "r"(dst), "l"(src) : "memory");
}
__device__ __forceinline__ void cp_commit() {
    asm volatile("cp.async.commit_group;" ::: "memory");
}
__device__ __forceinline__ void cp_wait1() {
    asm volatile("cp.async.wait_group 1;" ::: "memory");
}
__device__ __forceinline__ void cp_wait0() {
    asm volatile("cp.async.wait_group 0;" ::: "memory");
}
__device__ __forceinline__ void ldsm4(uint32_t* r, uint32_t addr) {
    asm volatile("ldmatrix.sync.aligned.m8n8.x4.shared.b16 {%0,%1,%2,%3}, [%4];"
                 : "=r"(r[0]), "=r"(r[1]), "=r"(r[2]), "=r"(r[3]) : "r"(addr));
}
__device__ __forceinline__ void mma_f16(float* d, const uint32_t* a, uint32_t b0, uint32_t b1) {
    asm volatile(
        "mma.sync.aligned.m16n8k16.row.col.f32.f16.f16.f32 "
        "{%0,%1,%2,%3}, {%4,%5,%6,%7}, {%8,%9}, {%0,%1,%2,%3};"
        : "+f"(d[0]), "+f"(d[1]), "+f"(d[2]), "+f"(d[3])
        : "r"(a[0]), "r"(a[1]), "r"(a[2]), "r"(a[3]), "r"(b0), "r"(b1));
}

// ---------------------------------------------------------------------------
__global__ void init_state(const float* __restrict__ h0, const float* __restrict__ c0) {
    int i = blockIdx.x * 256 + threadIdx.x;
    if (i < NG) g_ctr[i][0] = 0u;
    if (i < ROWS * HDIM) {
        g_h[0][i] = __float2half(h0[i]);
        g_c[i] = c0[i];
    }
}

// ---------------------------------------------------------------------------
// Repack W fp16 pre-swizzled: dst = j*98304 + g*8192 + n*64 + kl'
//   kl' = ((kl>>3) ^ (n&7))*8 + (kl&7);  unit = j*32 + (n>>2); gate = n&3;
//   value = W_gate[(1 + g*64 + kl)*768 + unit]
__global__ void repack(const float* __restrict__ Wi, const float* __restrict__ Wf,
                       const float* __restrict__ Wc, const float* __restrict__ Wo,
                       const float* __restrict__ bi, const float* __restrict__ bf,
                       const float* __restrict__ bc, const float* __restrict__ bo) {
    int idx = blockIdx.x * 256 + threadIdx.x;
    const int TOT = NJ * 98304;
    if (idx < TOT) {
        int kl = idx & 63;
        int n  = (idx >> 6) & 127;
        int g  = (idx >> 13) % 12;
        int j  = idx / 98304;
        int gate = n & 3;
        int unit = j * 32 + (n >> 2);
        const float* W = (gate == 0) ? Wi : (gate == 1) ? Wf : (gate == 2) ? Wc : Wo;
        float v = W[(1 + g * 64 + kl) * HDIM + unit];
        int dst = j * 98304 + g * 8192 + n * 64 + (((kl >> 3) ^ (n & 7)) << 3) + (kl & 7);
        g_W[dst] = __float2half(v);
    }
    if (idx < NJ * 128) {
        int n = idx & 127;
        int j = idx >> 7;
        int gate = n & 3;
        int unit = j * 32 + (n >> 2);
        const float* W = (gate == 0) ? Wi : (gate == 1) ? Wf : (gate == 2) ? Wc : Wo;
        const float* B = (gate == 0) ? bi : (gate == 1) ? bf : (gate == 2) ? bc : bo;
        g_wxb[idx] = make_float2(W[unit], B[unit]);
    }
}

// ---------------------------------------------------------------------------
__global__ void __launch_bounds__(512, 1) lstm_persistent(const float* __restrict__ x) {
    extern __shared__ char smem[];
    const uint32_t sb = smem_u32(smem);
    const int tid = threadIdx.x;
    const int lane = tid & 31, wid = tid >> 5;
    const int mw = wid & 1;          // row half: rows [16mw, 16mw+16) within group
    const int nw = wid >> 1;         // col block: gate cols [16nw, 16nw+16)
    const int nb = blockIdx.x;
    const int gi = nb / NJ;          // row group (rows [32gi, 32gi+32))
    const int jb = nb % NJ;          // unit block (units [32jb, 32jb+32))
    const uint32_t flag_addr = sb + FLAG_OFF;

    // ---------------- prologue: stage W slice into smem (192KB, once) --------
    {
        const uint4* __restrict__ sw = ((const uint4*)g_W) + jb * 12288;
        uint4* dw = (uint4*)(smem + WS_BASE);
        for (int i = tid; i < 12288; i += 512) dw[i] = sw[i];
        if (tid == 0) *(volatile unsigned*)(smem + FLAG_OFF) = 0u;
    }
    __syncthreads();

    // ldsm lane constants (XOR swizzle, pitch 128)
    const int sel = lane >> 3, li = lane & 7;
    const int hsA = sel >> 1, hsB = sel & 1;
    const uint32_t aoffrow = (uint32_t)((mw * 16 + li + (sel & 1) * 8) * 128);
    const uint32_t boffrow = (uint32_t)((nw * 16 + li + (sel >> 1) * 8) * 128);

    // epilogue constants
    const int my_row = gi * 32 + mw * 16 + (lane >> 2) + (lane & 1) * 8;
    const float* __restrict__ xrow = x + (my_row >> 1) * 512 + (my_row & 1);

    // registers: wxb + cell state (2 cells per lane: q = ntile 0,1)
    float2 wxi[2], wxf[2], wxc[2], wxo[2];
    float  creg[2];
#pragma unroll
    for (int q = 0; q < 2; ++q) {
        int jl = q * 2 + ((lane & 3) >> 1);        // local unit within warp's 4
        int nloc = (nw * 4 + jl) * 4;              // local col of gate i
        const float2* __restrict__ wxbp = g_wxb + jb * 128 + nloc;
        wxi[q] = wxbp[0];
        wxf[q] = wxbp[1];
        wxc[q] = wxbp[2];
        wxo[q] = wxbp[3];
        creg[q] = g_c[my_row * HDIM + jb * 32 + nw * 4 + jl];
    }

    // sync: one counter per row group; warp 0 lane 0 polls, flag fanout
    unsigned* __restrict__ relp = &g_ctr[gi][0];

    for (int t = 0; t < SEQ; ++t) {
        const int par = t & 1;
        const __half* __restrict__ hin = g_h[par];
        __half* __restrict__ hout = g_h[par ^ 1];

        // ---- dataflow wait: all 24 CTAs of this row group finished step t-1 --
        if (t > 0) {
            const unsigned tgt = 24u * (unsigned)t;
            if (wid == 0) {
                if (lane == 0) {
                    unsigned v;
                    do {
                        asm volatile("ld.acquire.gpu.global.u32 %0, [%1];"
                                     : "=r"(v) : "l"(relp) : "memory");
                    } while (v < tgt);
                    asm volatile("st.release.cta.shared.u32 [%0], %1;"
                                 :: "r"(flag_addr), "r"((unsigned)t) : "memory");
                }
                __syncwarp();
            } else {
                unsigned v;
                do {
                    asm volatile("ld.acquire.cta.shared.u32 %0, [%1];"
                                 : "=r"(v) : "r"(flag_addr) : "memory");
                } while (v < (unsigned)t);
            }
        }
        __syncwarp();

        float d[2][4];
#pragma unroll
        for (int q = 0; q < 2; ++q)
#pragma unroll
            for (int k = 0; k < 4; ++k) d[q][k] = 0.f;

        // CTA-wide A staging: chunk l = 32 rows x 128 k (8KB), all 512 threads
        auto issue = [&](int l) {
            const int sub = tid >> 8, row = (tid >> 3) & 31, seg = tid & 7;
            uint32_t dst = sb + A_BASE + (uint32_t)(l % 3) * 8192
                         + (uint32_t)(sub * 4096 + row * 128 + ((seg ^ (row & 7)) << 4));
            cpa16(dst, hin + (gi * 32 + row) * HDIM + l * 128 + sub * 64 + seg * 8);
            cp_commit();
        };

        issue(0); issue(1);

#pragma unroll
        for (int l = 0; l < 6; ++l) {
            if (l < 5) cp_wait1(); else cp_wait0();
            __syncthreads();                       // staged data visible to all
            if (l + 2 < 6) issue(l + 2);           // buf (l+2)%3: chunk l-1's, all done
            const uint32_t abuf = sb + A_BASE + (uint32_t)(l % 3) * 8192;
#pragma unroll
            for (int ks = 0; ks < 8; ++ks) {
                const int g = l * 2 + (ks >> 2);
                const uint32_t asw = (uint32_t)(((((ks & 3) << 1) | hsA) ^ li) << 4);
                const uint32_t bsw = (uint32_t)(((((ks & 3) << 1) | hsB) ^ li) << 4);
                uint32_t a[4], b[4];
                ldsm4(a, abuf + (uint32_t)((ks >> 2) * 4096) + aoffrow + asw);
                ldsm4(b, sb + WS_BASE + (uint32_t)(g * 16384) + boffrow + bsw);
                mma_f16(d[0], a, b[0], b[1]);
                mma_f16(d[1], a, b[2], b[3]);
            }
        }

        // ---------------- fused LSTM epilogue (no exchange needed) ------------
        const float xv = xrow[2 * t];
#pragma unroll
        for (int q = 0; q < 2; ++q) {
            const int jl = q * 2 + ((lane & 3) >> 1);
            float p0 = __shfl_xor_sync(0xffffffffu, d[q][0], 1);
            float p1 = __shfl_xor_sync(0xffffffffu, d[q][1], 1);
            float p2 = __shfl_xor_sync(0xffffffffu, d[q][2], 1);
            float p3 = __shfl_xor_sync(0xffffffffu, d[q][3], 1);
            float gI, gF, gC, gO;
            if (!(lane & 1)) { gI = d[q][0]; gF = d[q][1]; gC = p0; gO = p1; }
            else             { gI = p2;      gF = p3;      gC = d[q][2]; gO = d[q][3]; }
            float pi = gI + xv * wxi[q].x + wxi[q].y;
            float pf = gF + xv * wxf[q].x + wxf[q].y;
            float pc = gC + xv * wxc[q].x + wxc[q].y;
            float po = gO + xv * wxo[q].x + wxo[q].y;
            float ig = __fdividef(1.f, 1.f + __expf(-pi));
            float fg = __fdividef(1.f, 1.f + __expf(-pf));
            float thc = 1.f - __fdividef(2.f, 1.f + __expf(2.f * pc));
            float cn = fg * creg[q] + ig * thc;
            float thn = 1.f - __fdividef(2.f, 1.f + __expf(2.f * cn));
            float hn = po * thn;            // no sigmoid on output gate
            creg[q] = cn;
            hout[my_row * HDIM + jb * 32 + nw * 4 + jl] = __float2half(hn);
        }

        // publish: CTA sync orders all h stores before the single release-add
        if (t + 1 < SEQ) {
            __syncthreads();
            if (tid == 0) {
                asm volatile("red.release.gpu.global.add.u32 [%0], %1;"
                             :: "l"(relp), "r"(1u) : "memory");
            }
        }
    }
}

// ---------------------------------------------------------------------------
__global__ void out_final(const float* __restrict__ Wout,
                          const float* __restrict__ bout,
                          float* __restrict__ out) {
    int gtid = blockIdx.x * 128 + threadIdx.x;
    int r = gtid >> 5, lane = gtid & 31;
    float s = 0.f;
    for (int k = lane; k < HDIM; k += 32)
        s += __half2float(g_h[0][r * HDIM + k]) * Wout[k];
#pragma unroll
    for (int o = 16; o; o >>= 1) s += __shfl_xor_sync(0xffffffffu, s, o);
    if (lane == 0) out[r] = s + bout[0];
}

// ---------------------------------------------------------------------------
extern "C" void kernel_launch(void* const* d_in, const int* in_sizes, int n_in,
                              void* d_out, int out_size) {
    (void)in_sizes; (void)n_in; (void)out_size;
    const float* x    = (const float*)d_in[0];
    const float* h0   = (const float*)d_in[1];
    const float* c0   = (const float*)d_in[2];
    const float* Wi   = (const float*)d_in[3];
    const float* bi   = (const float*)d_in[4];
    const float* Wf   = (const float*)d_in[5];
    const float* bf   = (const float*)d_in[6];
    const float* Wc   = (const float*)d_in[7];
    const float* bc   = (const float*)d_in[8];
    const float* Wo   = (const float*)d_in[9];
    const float* bo   = (const float*)d_in[10];
    const float* Wout = (const float*)d_in[11];
    const float* bout = (const float*)d_in[12];
    float* out = (float*)d_out;

    static int configured = 0;
    if (!configured) {
        cudaFuncSetAttribute(lstm_persistent,
                             cudaFuncAttributeMaxDynamicSharedMemorySize, SMEM_TOTAL);
        configured = 1;
    }

    init_state<<<(ROWS * HDIM + 255) / 256, 256>>>(h0, c0);
    repack<<<(NJ * 98304 + 255) / 256, 256>>>(Wi, Wf, Wc, Wo, bi, bf, bc, bo);
    lstm_persistent<<<NCTA, 512, SMEM_TOTAL>>>(x);
    out_final<<<32, 128>>>(Wout, bout, out);
}

// round 17
// speedup vs baseline: 1.4633x; 1.0257x over previous
#include <cuda_runtime.h>
#include <cuda_fp16.h>
#include <math.h>
#include <stdint.h>

// VanillaLSTM persistent kernel (sm_103 HMMA fp16), 2D row x unit partition.
// 96 CTAs = 4 row-groups (32 rows) x 24 unit-blocks (32 hidden units, N=128
// gate cols). Full K=768 per CTA; W slice (192KB fp16) SMEM-resident.
// Row groups are independent recurrences; sync = 1 counter per group (24 CTAs).
// R17: A staged CTA-wide in 3 chunks of 256k (16KB), 2 buffers, 3 barriers
// per step (was 6). 512 threads: warp (mw,nw) = rows x gate-col tile 16x16.

#define ROWS 128
#define HDIM 768
#define SEQ  256
#define NCTA 96
#define NJ   24      // unit blocks
#define NG   4       // row groups

// smem layout (bytes)
#define WS_BASE 0                 // 12 blocks x 16KB = 196608
#define A_BASE 196608             // 2 bufs x 16384 = 32768
#define FLAG_OFF 229376
#define SMEM_TOTAL 229504

__device__ __align__(16) __half        g_h[2][ROWS * HDIM];
__device__ __align__(16) float         g_c[ROWS * HDIM];
__device__ __align__(16) __half        g_W[NJ * 98304];     // [j][g(12)][n(128)][kl(64) swizzled]
__device__ __align__(16) float2        g_wxb[NJ * 128];     // [j][n]: (W_row0, bias)
__device__ __align__(128) unsigned     g_ctr[NG][32];       // one per row-group

// ---------------------------------------------------------------------------
__device__ __forceinline__ uint32_t smem_u32(const void* p) {
    uint32_t a;
    asm("{ .reg .u64 t; cvta.to.shared.u64 t, %1; cvt.u32.u64 %0, t; }" : "=r"(a) : "l"(p));
    return a;
}
__device__ __forceinline__ void cpa16(uint32_t dst, const void* src) {
    asm volatile("cp.async.cg.shared.global [%0], [%1], 16;" :: "r"(dst), "l"(src) : "memory");
}
__device__ __forceinline__ void cp_commit() {
    asm volatile("cp.async.commit_group;" ::: "memory");
}
__device__ __forceinline__ void cp_wait1() {
    asm volatile("cp.async.wait_group 1;" ::: "memory");
}
__device__ __forceinline__ void cp_wait0() {
    asm volatile("cp.async.wait_group 0;" ::: "memory");
}
__device__ __forceinline__ void ldsm4(uint32_t* r, uint32_t addr) {
    asm volatile("ldmatrix.sync.aligned.m8n8.x4.shared.b16 {%0,%1,%2,%3}, [%4];"
                 : "=r"(r[0]), "=r"(r[1]), "=r"(r[2]), "=r"(r[3]) : "r"(addr));
}
__device__ __forceinline__ void mma_f16(float* d, const uint32_t* a, uint32_t b0, uint32_t b1) {
    asm volatile(
        "mma.sync.aligned.m16n8k16.row.col.f32.f16.f16.f32 "
        "{%0,%1,%2,%3}, {%4,%5,%6,%7}, {%8,%9}, {%0,%1,%2,%3};"
        : "+f"(d[0]), "+f"(d[1]), "+f"(d[2]), "+f"(d[3])
        : "r"(a[0]), "r"(a[1]), "r"(a[2]), "r"(a[3]), "r"(b0), "r"(b1));
}

// ---------------------------------------------------------------------------
__global__ void init_state(const float* __restrict__ h0, const float* __restrict__ c0) {
    int i = blockIdx.x * 256 + threadIdx.x;
    if (i < NG) g_ctr[i][0] = 0u;
    if (i < ROWS * HDIM) {
        g_h[0][i] = __float2half(h0[i]);
        g_c[i] = c0[i];
    }
}

// ---------------------------------------------------------------------------
// Repack W fp16 pre-swizzled: dst = j*98304 + g*8192 + n*64 + kl'
//   kl' = ((kl>>3) ^ (n&7))*8 + (kl&7);  unit = j*32 + (n>>2); gate = n&3;
//   value = W_gate[(1 + g*64 + kl)*768 + unit]
__global__ void repack(const float* __restrict__ Wi, const float* __restrict__ Wf,
                       const float* __restrict__ Wc, const float* __restrict__ Wo,
                       const float* __restrict__ bi, const float* __restrict__ bf,
                       const float* __restrict__ bc, const float* __restrict__ bo) {
    int idx = blockIdx.x * 256 + threadIdx.x;
    const int TOT = NJ * 98304;
    if (idx < TOT) {
        int kl = idx & 63;
        int n  = (idx >> 6) & 127;
        int g  = (idx >> 13) % 12;
        int j  = idx / 98304;
        int gate = n & 3;
        int unit = j * 32 + (n >> 2);
        const float* W = (gate == 0) ? Wi : (gate == 1) ? Wf : (gate == 2) ? Wc : Wo;
        float v = W[(1 + g * 64 + kl) * HDIM + unit];
        int dst = j * 98304 + g * 8192 + n * 64 + (((kl >> 3) ^ (n & 7)) << 3) + (kl & 7);
        g_W[dst] = __float2half(v);
    }
    if (idx < NJ * 128) {
        int n = idx & 127;
        int j = idx >> 7;
        int gate = n & 3;
        int unit = j * 32 + (n >> 2);
        const float* W = (gate == 0) ? Wi : (gate == 1) ? Wf : (gate == 2) ? Wc : Wo;
        const float* B = (gate == 0) ? bi : (gate == 1) ? bf : (gate == 2) ? bc : bo;
        g_wxb[idx] = make_float2(W[unit], B[unit]);
    }
}

// ---------------------------------------------------------------------------
__global__ void __launch_bounds__(512, 1) lstm_persistent(const float* __restrict__ x) {
    extern __shared__ char smem[];
    const uint32_t sb = smem_u32(smem);
    const int tid = threadIdx.x;
    const int lane = tid & 31, wid = tid >> 5;
    const int mw = wid & 1;          // row half: rows [16mw, 16mw+16) within group
    const int nw = wid >> 1;         // col block: gate cols [16nw, 16nw+16)
    const int nb = blockIdx.x;
    const int gi = nb / NJ;          // row group (rows [32gi, 32gi+32))
    const int jb = nb % NJ;          // unit block (units [32jb, 32jb+32))
    const uint32_t flag_addr = sb + FLAG_OFF;

    // ---------------- prologue: stage W slice into smem (192KB, once) --------
    {
        const uint4* __restrict__ sw = ((const uint4*)g_W) + jb * 12288;
        uint4* dw = (uint4*)(smem + WS_BASE);
        for (int i = tid; i < 12288; i += 512) dw[i] = sw[i];
        if (tid == 0) *(volatile unsigned*)(smem + FLAG_OFF) = 0u;
    }
    __syncthreads();

    // ldsm lane constants (XOR swizzle, pitch 128)
    const int sel = lane >> 3, li = lane & 7;
    const int hsA = sel >> 1, hsB = sel & 1;
    const uint32_t aoffrow = (uint32_t)((mw * 16 + li + (sel & 1) * 8) * 128);
    const uint32_t boffrow = (uint32_t)((nw * 16 + li + (sel >> 1) * 8) * 128);

    // epilogue constants
    const int my_row = gi * 32 + mw * 16 + (lane >> 2) + (lane & 1) * 8;
    const float* __restrict__ xrow = x + (my_row >> 1) * 512 + (my_row & 1);

    // registers: wxb + cell state (2 cells per lane: q = ntile 0,1)
    float2 wxi[2], wxf[2], wxc[2], wxo[2];
    float  creg[2];
#pragma unroll
    for (int q = 0; q < 2; ++q) {
        int jl = q * 2 + ((lane & 3) >> 1);        // local unit within warp's 4
        int nloc = (nw * 4 + jl) * 4;              // local col of gate i
        const float2* __restrict__ wxbp = g_wxb + jb * 128 + nloc;
        wxi[q] = wxbp[0];
        wxf[q] = wxbp[1];
        wxc[q] = wxbp[2];
        wxo[q] = wxbp[3];
        creg[q] = g_c[my_row * HDIM + jb * 32 + nw * 4 + jl];
    }

    // sync: one counter per row group; warp 0 lane 0 polls, flag fanout
    unsigned* __restrict__ relp = &g_ctr[gi][0];

    for (int t = 0; t < SEQ; ++t) {
        const int par = t & 1;
        const __half* __restrict__ hin = g_h[par];
        __half* __restrict__ hout = g_h[par ^ 1];

        // ---- dataflow wait: all 24 CTAs of this row group finished step t-1 --
        if (t > 0) {
            const unsigned tgt = 24u * (unsigned)t;
            if (wid == 0) {
                if (lane == 0) {
                    unsigned v;
                    do {
                        asm volatile("ld.acquire.gpu.global.u32 %0, [%1];"
                                     : "=r"(v) : "l"(relp) : "memory");
                    } while (v < tgt);
                    asm volatile("st.release.cta.shared.u32 [%0], %1;"
                                 :: "r"(flag_addr), "r"((unsigned)t) : "memory");
                }
                __syncwarp();
            } else {
                unsigned v;
                do {
                    asm volatile("ld.acquire.cta.shared.u32 %0, [%1];"
                                 : "=r"(v) : "r"(flag_addr) : "memory");
                } while (v < (unsigned)t);
            }
        }
        __syncwarp();

        float d[2][4];
#pragma unroll
        for (int q = 0; q < 2; ++q)
#pragma unroll
            for (int k = 0; k < 4; ++k) d[q][k] = 0.f;

        // CTA-wide A staging: chunk l = 32 rows x 256 k (16KB), 2 buffers.
        // Layout: [sub(4) of 64k][row(32)][128B swizzled].
        auto issue = [&](int l) {
            const uint32_t bufs = sb + A_BASE + (uint32_t)(l & 1) * 16384;
#pragma unroll
            for (int i = 0; i < 2; ++i) {
                int idx = tid + 512 * i;           // 0..1023
                int sub = idx >> 8, row = (idx >> 3) & 31, seg = idx & 7;
                uint32_t dst = bufs + (uint32_t)(sub * 4096 + row * 128
                                                 + ((seg ^ (row & 7)) << 4));
                cpa16(dst, hin + (gi * 32 + row) * HDIM + l * 256 + sub * 64 + seg * 8);
            }
            cp_commit();
        };

        issue(0); issue(1);

#pragma unroll
        for (int l = 0; l < 3; ++l) {
            if (l < 2) cp_wait1(); else cp_wait0();
            __syncthreads();                       // chunk l visible to all; also
                                                   // orders prior chunk's reads
            if (l == 1) issue(2);                  // buf0 free (chunk0 consumed)
            const uint32_t abuf = sb + A_BASE + (uint32_t)(l & 1) * 16384;
#pragma unroll
            for (int ks = 0; ks < 16; ++ks) {
                const int g = l * 4 + (ks >> 2);
                const uint32_t asw = (uint32_t)(((((ks & 3) << 1) | hsA) ^ li) << 4);
                const uint32_t bsw = (uint32_t)(((((ks & 3) << 1) | hsB) ^ li) << 4);
                uint32_t a[4], b[4];
                ldsm4(a, abuf + (uint32_t)((ks >> 2) * 4096) + aoffrow + asw);
                ldsm4(b, sb + WS_BASE + (uint32_t)(g * 16384) + boffrow + bsw);
                mma_f16(d[0], a, b[0], b[1]);
                mma_f16(d[1], a, b[2], b[3]);
            }
        }

        // ---------------- fused LSTM epilogue (no exchange needed) ------------
        const float xv = xrow[2 * t];
#pragma unroll
        for (int q = 0; q < 2; ++q) {
            const int jl = q * 2 + ((lane & 3) >> 1);
            float p0 = __shfl_xor_sync(0xffffffffu, d[q][0], 1);
            float p1 = __shfl_xor_sync(0xffffffffu, d[q][1], 1);
            float p2 = __shfl_xor_sync(0xffffffffu, d[q][2], 1);
            float p3 = __shfl_xor_sync(0xffffffffu, d[q][3], 1);
            float gI, gF, gC, gO;
            if (!(lane & 1)) { gI = d[q][0]; gF = d[q][1]; gC = p0; gO = p1; }
            else             { gI = p2;      gF = p3;      gC = d[q][2]; gO = d[q][3]; }
            float pi = gI + xv * wxi[q].x + wxi[q].y;
            float pf = gF + xv * wxf[q].x + wxf[q].y;
            float pc = gC + xv * wxc[q].x + wxc[q].y;
            float po = gO + xv * wxo[q].x + wxo[q].y;
            float ig = __fdividef(1.f, 1.f + __expf(-pi));
            float fg = __fdividef(1.f, 1.f + __expf(-pf));
            float thc = 1.f - __fdividef(2.f, 1.f + __expf(2.f * pc));
            float cn = fg * creg[q] + ig * thc;
            float thn = 1.f - __fdividef(2.f, 1.f + __expf(2.f * cn));
            float hn = po * thn;            // no sigmoid on output gate
            creg[q] = cn;
            hout[my_row * HDIM + jb * 32 + nw * 4 + jl] = __float2half(hn);
        }

        // publish: CTA sync orders all h stores before the single release-add
        if (t + 1 < SEQ) {
            __syncthreads();
            if (tid == 0) {
                asm volatile("red.release.gpu.global.add.u32 [%0], %1;"
                             :: "l"(relp), "r"(1u) : "memory");
            }
        }
    }
}

// ---------------------------------------------------------------------------
__global__ void out_final(const float* __restrict__ Wout,
                          const float* __restrict__ bout,
                          float* __restrict__ out) {
    int gtid = blockIdx.x * 128 + threadIdx.x;
    int r = gtid >> 5, lane = gtid & 31;
    float s = 0.f;
    for (int k = lane; k < HDIM; k += 32)
        s += __half2float(g_h[0][r * HDIM + k]) * Wout[k];
#pragma unroll
    for (int o = 16; o; o >>= 1) s += __shfl_xor_sync(0xffffffffu, s, o);
    if (lane == 0) out[r] = s + bout[0];
}

// ---------------------------------------------------------------------------
extern "C" void kernel_launch(void* const* d_in, const int* in_sizes, int n_in,
                              void* d_out, int out_size) {
    (void)in_sizes; (void)n_in; (void)out_size;
    const float* x    = (const float*)d_in[0];
    const float* h0   = (const float*)d_in[1];
    const float* c0   = (const float*)d_in[2];
    const float* Wi   = (const float*)d_in[3];
    const float* bi   = (const float*)d_in[4];
    const float* Wf   = (const float*)d_in[5];
    const float* bf   = (const float*)d_in[6];
    const float* Wc   = (const float*)d_in[7];
    const float* bc   = (const float*)d_in[8];
    const float* Wo   = (const float*)d_in[9];
    const float* bo   = (const float*)d_in[10];
    const float* Wout = (const float*)d_in[11];
    const float* bout = (const float*)d_in[12];
    float* out = (float*)d_out;

    static int configured = 0;
    if (!configured) {
        cudaFuncSetAttribute(lstm_persistent,
                             cudaFuncAttributeMaxDynamicSharedMemorySize, SMEM_TOTAL);
        configured = 1;
    }

    init_state<<<(ROWS * HDIM + 255) / 256, 256>>>(h0, c0);
    repack<<<(NJ * 98304 + 255) / 256, 256>>>(Wi, Wf, Wc, Wo, bi, bf, bc, bo);
    lstm_persistent<<<NCTA, 512, SMEM_TOTAL>>>(x);
    out_final<<<32, 128>>>(Wout, bout, out);
}